// round 1
// baseline (speedup 1.0000x reference)
#include <cuda_runtime.h>
#include <math.h>

#define HIDDEN   2048
#define NHEADS   16
#define HDIM     128
#define BATCH    2
#define SEQ      2048
#define BH       (BATCH * NHEADS)
#define MROWS    (BATCH * SEQ)
#define INV_NORM 0.08838834764831845f   // 1/sqrt(128)

// ---------------- scratch (static __device__ — no allocation) ----------------
__device__ __align__(16) float g_q[(size_t)BH * SEQ * HDIM];          // [b*16+h][s][d]
__device__ __align__(16) float g_k[(size_t)BH * SEQ * HDIM];          // [b*16+h][s][d]
__device__ __align__(16) float g_vT[(size_t)BH * HDIM * SEQ];         // [b*16+h][d][s]
__device__ __align__(16) float g_scores[(size_t)BH * SEQ * SEQ];      // [bh][q][k]  (512 MB)
__device__ __align__(16) float g_ctx[(size_t)MROWS * HIDDEN];         // [b*S+s][h*128+d]

// ---------------- shared SGEMM core: C(128x128) += A(128xK) * B(128xK)^T -----
// A: row-major [128][K] (lda), B: row-major [128][K] (ldb). NT GEMM.
// 256 threads, each computes an 8x8 micro-tile. BK = 8.
__device__ __forceinline__ void sgemm_core(const float* __restrict__ A,
                                           const float* __restrict__ B,
                                           int K, int lda, int ldb,
                                           float (&acc)[8][8]) {
    __shared__ float As[8][128];
    __shared__ float Bs[8][128];
    const int tid  = threadIdx.x;
    const int lrow = tid >> 1;          // 0..127
    const int lcol = (tid & 1) << 2;    // 0 or 4
    const int ty   = tid >> 4;          // 0..15
    const int tx   = tid & 15;          // 0..15

    const float* Aptr = A + (size_t)lrow * lda + lcol;
    const float* Bptr = B + (size_t)lrow * ldb + lcol;

    for (int k0 = 0; k0 < K; k0 += 8) {
        float4 av = *(const float4*)(Aptr + k0);
        float4 bv = *(const float4*)(Bptr + k0);
        __syncthreads();
        As[lcol + 0][lrow] = av.x; As[lcol + 1][lrow] = av.y;
        As[lcol + 2][lrow] = av.z; As[lcol + 3][lrow] = av.w;
        Bs[lcol + 0][lrow] = bv.x; Bs[lcol + 1][lrow] = bv.y;
        Bs[lcol + 2][lrow] = bv.z; Bs[lcol + 3][lrow] = bv.w;
        __syncthreads();
#pragma unroll
        for (int k = 0; k < 8; k++) {
            float a[8], b[8];
#pragma unroll
            for (int i = 0; i < 8; i++) a[i] = As[k][ty * 8 + i];
#pragma unroll
            for (int j = 0; j < 8; j++) b[j] = Bs[k][tx * 8 + j];
#pragma unroll
            for (int i = 0; i < 8; i++)
#pragma unroll
                for (int j = 0; j < 8; j++)
                    acc[i][j] = fmaf(a[i], b[j], acc[i][j]);
        }
    }
}

// ---------------- 1) fused QKV projection ------------------------------------
// grid: (N/128=16, M/128=32, 3). z selects Q/K/V. Writes head-major layouts.
__global__ void __launch_bounds__(256)
qkv_kernel(const float* __restrict__ X,
           const float* __restrict__ Wq, const float* __restrict__ bq,
           const float* __restrict__ Wk, const float* __restrict__ bk,
           const float* __restrict__ Wv, const float* __restrict__ bv) {
    const int which = blockIdx.z;
    const float* W    = (which == 0) ? Wq : (which == 1) ? Wk : Wv;
    const float* bias = (which == 0) ? bq : (which == 1) ? bk : bv;

    float acc[8][8] = {};
    const float* A  = X + (size_t)blockIdx.y * 128 * HIDDEN;
    const float* Bm = W + (size_t)blockIdx.x * 128 * HIDDEN;
    sgemm_core(A, Bm, HIDDEN, HIDDEN, HIDDEN, acc);

    const int ty = threadIdx.x >> 4, tx = threadIdx.x & 15;
    const int m0 = blockIdx.y * 128 + ty * 8;
    const int n0 = blockIdx.x * 128 + tx * 8;
    const int h  = blockIdx.x;  // BN == HDIM → one head per column block
#pragma unroll
    for (int i = 0; i < 8; i++) {
        const int m = m0 + i;
        const int b = m >> 11;            // /SEQ
        const int s = m & (SEQ - 1);
#pragma unroll
        for (int j = 0; j < 8; j++) {
            const int n = n0 + j;
            const int d = n & (HDIM - 1);
            const float v = acc[i][j] + bias[n];
            if (which == 2) {
                g_vT[((size_t)(b * NHEADS + h) * HDIM + d) * SEQ + s] = v;
            } else {
                float* dst = (which == 0) ? g_q : g_k;
                dst[((size_t)(b * NHEADS + h) * SEQ + s) * HDIM + d] = v;
            }
        }
    }
}

// ---------------- 2) scores = beta*alibi + inv_norm * Q K^T ------------------
// grid: (16, 16, 32)
__global__ void __launch_bounds__(256)
scores_kernel(const float* __restrict__ alibi) {
    const int z = blockIdx.z;
    const float* A  = g_q + (size_t)z * SEQ * HDIM + (size_t)blockIdx.y * 128 * HDIM;
    const float* Bm = g_k + (size_t)z * SEQ * HDIM + (size_t)blockIdx.x * 128 * HDIM;
    float acc[8][8] = {};
    sgemm_core(A, Bm, HDIM, HDIM, HDIM, acc);

    float* C = g_scores + (size_t)z * SEQ * SEQ;
    const float* al = alibi + (size_t)z * SEQ;
    const int ty = threadIdx.x >> 4, tx = threadIdx.x & 15;
    const int m0 = blockIdx.y * 128 + ty * 8;
    const int n0 = blockIdx.x * 128 + tx * 8;
#pragma unroll
    for (int i = 0; i < 8; i++)
#pragma unroll
        for (int j = 0; j < 8; j++) {
            const int n = n0 + j;
            C[(size_t)(m0 + i) * SEQ + n] = al[n] + INV_NORM * acc[i][j];
        }
}

// ---------------- 3) rowwise softmax over 2048 keys --------------------------
// one 256-thread block per row; BH*SEQ = 65536 rows
__global__ void __launch_bounds__(256)
softmax_kernel() {
    float* p = g_scores + (size_t)blockIdx.x * SEQ;
    const int tid = threadIdx.x;
    __shared__ float red[256];

    float vals[8];
    float lmax = -INFINITY;
#pragma unroll
    for (int i = 0; i < 8; i++) {
        vals[i] = p[tid + i * 256];
        lmax = fmaxf(lmax, vals[i]);
    }
    red[tid] = lmax;
    __syncthreads();
    for (int s = 128; s > 0; s >>= 1) {
        if (tid < s) red[tid] = fmaxf(red[tid], red[tid + s]);
        __syncthreads();
    }
    const float rmax = red[0];
    __syncthreads();

    float lsum = 0.f;
#pragma unroll
    for (int i = 0; i < 8; i++) {
        vals[i] = __expf(vals[i] - rmax);
        lsum += vals[i];
    }
    red[tid] = lsum;
    __syncthreads();
    for (int s = 128; s > 0; s >>= 1) {
        if (tid < s) red[tid] += red[tid + s];
        __syncthreads();
    }
    const float rinv = 1.0f / red[0];
#pragma unroll
    for (int i = 0; i < 8; i++) p[tid + i * 256] = vals[i] * rinv;
}

// ---------------- 4) ctx = P @ V  (via V^T, NT) ------------------------------
// grid: (1, 16, 32). Writes directly into flat [b*S+s][h*128+d].
__global__ void __launch_bounds__(256)
ctx_kernel() {
    const int z = blockIdx.z;
    const float* A  = g_scores + (size_t)z * SEQ * SEQ + (size_t)blockIdx.y * 128 * SEQ;
    const float* Bm = g_vT + (size_t)z * HDIM * SEQ;
    float acc[8][8] = {};
    sgemm_core(A, Bm, SEQ, SEQ, SEQ, acc);

    const int b = z / NHEADS, h = z % NHEADS;
    const int ty = threadIdx.x >> 4, tx = threadIdx.x & 15;
    const int m0 = blockIdx.y * 128 + ty * 8;  // s
    const int n0 = tx * 8;                     // d
#pragma unroll
    for (int i = 0; i < 8; i++)
#pragma unroll
        for (int j = 0; j < 8; j++)
            g_ctx[(size_t)(b * SEQ + m0 + i) * HIDDEN + h * HDIM + n0 + j] = acc[i][j];
}

// ---------------- 5) out = ctx @ Wd^T + bd + residual ------------------------
// grid: (16, 32)
__global__ void __launch_bounds__(256)
out_kernel(const float* __restrict__ Wd, const float* __restrict__ bd,
           const float* __restrict__ residual, float* __restrict__ out) {
    const float* A  = g_ctx + (size_t)blockIdx.y * 128 * HIDDEN;
    const float* Bm = Wd + (size_t)blockIdx.x * 128 * HIDDEN;
    float acc[8][8] = {};
    sgemm_core(A, Bm, HIDDEN, HIDDEN, HIDDEN, acc);

    const int ty = threadIdx.x >> 4, tx = threadIdx.x & 15;
    const int m0 = blockIdx.y * 128 + ty * 8;
    const int n0 = blockIdx.x * 128 + tx * 8;
#pragma unroll
    for (int i = 0; i < 8; i++)
#pragma unroll
        for (int j = 0; j < 8; j++) {
            const size_t idx = (size_t)(m0 + i) * HIDDEN + (n0 + j);
            out[idx] = acc[i][j] + bd[n0 + j] + residual[idx];
        }
}

// ---------------- launch ------------------------------------------------------
extern "C" void kernel_launch(void* const* d_in, const int* in_sizes, int n_in,
                              void* d_out, int out_size) {
    const float* X        = (const float*)d_in[0];
    const float* residual = (const float*)d_in[1];
    const float* alibi    = (const float*)d_in[2];
    const float* Wq = (const float*)d_in[3];  const float* bq = (const float*)d_in[4];
    const float* Wk = (const float*)d_in[5];  const float* bk = (const float*)d_in[6];
    const float* Wv = (const float*)d_in[7];  const float* bv = (const float*)d_in[8];
    const float* Wd = (const float*)d_in[9];  const float* bd = (const float*)d_in[10];
    float* out = (float*)d_out;

    dim3 blk(256);
    qkv_kernel<<<dim3(16, 32, 3), blk>>>(X, Wq, bq, Wk, bk, Wv, bv);
    scores_kernel<<<dim3(16, 16, 32), blk>>>(alibi);
    softmax_kernel<<<dim3(BH * SEQ), blk>>>();
    ctx_kernel<<<dim3(1, 16, 32), blk>>>();
    out_kernel<<<dim3(16, 32, 1), blk>>>(Wd, bd, residual, out);
}

// round 3
// speedup vs baseline: 3.1523x; 3.1523x over previous
#include <cuda_runtime.h>
#include <cuda_bf16.h>
#include <math.h>
#include <stdint.h>

#define HIDDEN   2048
#define NHEADS   16
#define HDIM     128
#define BATCH    2
#define SEQ      2048
#define BH       (BATCH * NHEADS)
#define MROWS    (BATCH * SEQ)
#define INV_NORM 0.08838834764831845f   // 1/sqrt(128)

#define KB        32                    // K elems per chunk
#define STAGE_B   32768                 // 4 tiles x 128x32 bf16 (8KB each)
#define NSTAGE    3
#define EPI_STR   132
#define SMEM_DYN  (NSTAGE * STAGE_B)    // 98304 > 128*132*4 epilogue area

// ===================== scratch (static __device__, no allocation) ============
__device__ __align__(128) float g_scores[(size_t)BH * SEQ * SEQ];          // 512MB

__device__ __align__(128) __nv_bfloat16 g_xh[(size_t)MROWS * HIDDEN];
__device__ __align__(128) __nv_bfloat16 g_xl[(size_t)MROWS * HIDDEN];
__device__ __align__(128) __nv_bfloat16 g_wqh[(size_t)HIDDEN * HIDDEN];
__device__ __align__(128) __nv_bfloat16 g_wql[(size_t)HIDDEN * HIDDEN];
__device__ __align__(128) __nv_bfloat16 g_wkh[(size_t)HIDDEN * HIDDEN];
__device__ __align__(128) __nv_bfloat16 g_wkl[(size_t)HIDDEN * HIDDEN];
__device__ __align__(128) __nv_bfloat16 g_wvh[(size_t)HIDDEN * HIDDEN];
__device__ __align__(128) __nv_bfloat16 g_wvl[(size_t)HIDDEN * HIDDEN];
__device__ __align__(128) __nv_bfloat16 g_wdh[(size_t)HIDDEN * HIDDEN];
__device__ __align__(128) __nv_bfloat16 g_wdl[(size_t)HIDDEN * HIDDEN];

__device__ __align__(128) __nv_bfloat16 g_qh[(size_t)BH * SEQ * HDIM];
__device__ __align__(128) __nv_bfloat16 g_ql[(size_t)BH * SEQ * HDIM];
__device__ __align__(128) __nv_bfloat16 g_kh[(size_t)BH * SEQ * HDIM];
__device__ __align__(128) __nv_bfloat16 g_kl[(size_t)BH * SEQ * HDIM];
__device__ __align__(128) __nv_bfloat16 g_vTh[(size_t)BH * HDIM * SEQ];
__device__ __align__(128) __nv_bfloat16 g_vTl[(size_t)BH * HDIM * SEQ];
__device__ __align__(128) __nv_bfloat16 g_ph[(size_t)BH * SEQ * SEQ];      // 256MB
__device__ __align__(128) __nv_bfloat16 g_pl[(size_t)BH * SEQ * SEQ];      // 256MB
__device__ __align__(128) __nv_bfloat16 g_ch[(size_t)MROWS * HIDDEN];
__device__ __align__(128) __nv_bfloat16 g_cl[(size_t)MROWS * HIDDEN];

// ===================== helpers ===============================================
static __device__ __forceinline__ uint32_t s2u(const void* p) {
    uint32_t a;
    asm("{ .reg .u64 t; cvta.to.shared.u64 t, %1; cvt.u32.u64 %0, t; }"
        : "=r"(a) : "l"(p));
    return a;
}
static __device__ __forceinline__ void ldm4(uint32_t (&r)[4], uint32_t addr) {
    asm volatile("ldmatrix.sync.aligned.m8n8.x4.shared.b16 {%0,%1,%2,%3}, [%4];"
                 : "=r"(r[0]), "=r"(r[1]), "=r"(r[2]), "=r"(r[3]) : "r"(addr));
}
static __device__ __forceinline__ void mma16816(float (&c)[4],
                                                const uint32_t (&a)[4],
                                                const uint32_t* b) {
    asm volatile("mma.sync.aligned.m16n8k16.row.col.f32.bf16.bf16.f32 "
                 "{%0,%1,%2,%3}, {%4,%5,%6,%7}, {%8,%9}, {%0,%1,%2,%3};"
                 : "+f"(c[0]), "+f"(c[1]), "+f"(c[2]), "+f"(c[3])
                 : "r"(a[0]), "r"(a[1]), "r"(a[2]), "r"(a[3]),
                   "r"(b[0]), "r"(b[1]));
}
static __device__ __forceinline__ void split_bf(float x, __nv_bfloat16& h,
                                                __nv_bfloat16& l) {
    h = __float2bfloat16(x);
    l = __float2bfloat16(x - __bfloat162float(h));
}
// swizzled smem offset inside one 128x32 bf16 tile (row 64B, 16B lanes)
static __device__ __forceinline__ uint32_t swz(int row, int c16) {
    return (uint32_t)(row * 64 + ((c16 ^ ((row >> 1) & 3)) << 4));
}

// ===================== bf16x3 mma.sync GEMM core =============================
// C[128x128] = Ahi/lo[128xK] @ (Bhi/lo[128xK])^T, fp32 acc. NT, K-contig rows.
static __device__ __forceinline__ void mma_gemm(
    const __nv_bfloat16* __restrict__ Ah, const __nv_bfloat16* __restrict__ Al,
    const __nv_bfloat16* __restrict__ Bh, const __nv_bfloat16* __restrict__ Bl,
    int K, int lda, int ldb, float (&acc)[4][4][4]) {
    extern __shared__ char smem[];
    const uint32_t sb = s2u(smem);
    const int tid  = threadIdx.x;
    const int lane = tid & 31;
    const int wid  = tid >> 5;
    const int wm   = wid & 1;       // 2 warp rows (m)
    const int wn   = wid >> 1;      // 4 warp cols (n)
    const int NC   = K >> 5;

    const __nv_bfloat16* srcs[4] = { Ah, Al, Bh, Bl };
    const int lds[4] = { lda, lda, ldb, ldb };

    const int lrow = tid >> 2;          // 0..63 for rep loads
    const int lc16 = tid & 3;

#define ISSUE(cc)                                                              \
    {                                                                          \
        const int _c = (cc);                                                   \
        const uint32_t sbase = sb + (_c % NSTAGE) * STAGE_B;                   \
        _Pragma("unroll")                                                      \
        for (int mat = 0; mat < 4; mat++) {                                    \
            _Pragma("unroll")                                                  \
            for (int rep = 0; rep < 2; rep++) {                                \
                const int row = lrow + rep * 64;                               \
                const char* g = (const char*)(srcs[mat] +                      \
                                  (size_t)row * lds[mat] + _c * KB) + lc16*16; \
                const uint32_t so = sbase + mat * 8192 + swz(row, lc16);       \
                asm volatile("cp.async.cg.shared.global [%0], [%1], 16;"       \
                             :: "r"(so), "l"(g));                              \
            }                                                                  \
        }                                                                      \
        asm volatile("cp.async.commit_group;" ::: "memory");                   \
    }

    ISSUE(0);
    if (NC > 1) ISSUE(1);

    const int arow_in = lane & 15;
    const int akh     = lane >> 4;
    const int brow_in = ((lane >> 4) << 3) + (lane & 7);
    const int bkh     = (lane >> 3) & 1;

    for (int c = 0; c < NC; c++) {
        __syncthreads();                    // all warps done with stage (c-1)
        if (c + 2 < NC) {
            ISSUE(c + 2);
            asm volatile("cp.async.wait_group 2;" ::: "memory");
        } else if (c + 1 < NC) {
            asm volatile("cp.async.wait_group 1;" ::: "memory");
        } else {
            asm volatile("cp.async.wait_group 0;" ::: "memory");
        }
        __syncthreads();                    // stage c visible to all

        const uint32_t st = sb + (c % NSTAGE) * STAGE_B;
#pragma unroll
        for (int kk = 0; kk < 2; kk++) {
            uint32_t aH[4][4], aL[4][4], bH[2][4], bL[2][4];
#pragma unroll
            for (int mi = 0; mi < 4; mi++) {
                const int row = wm * 64 + mi * 16 + arow_in;
                const uint32_t ad = st + swz(row, kk * 2 + akh);
                ldm4(aH[mi], ad);
                ldm4(aL[mi], ad + 8192);
            }
#pragma unroll
            for (int nj = 0; nj < 2; nj++) {
                const int row = wn * 32 + nj * 16 + brow_in;
                const uint32_t bd = st + 16384 + swz(row, kk * 2 + bkh);
                ldm4(bH[nj], bd);
                ldm4(bL[nj], bd + 8192);
            }
#pragma unroll
            for (int mi = 0; mi < 4; mi++)
#pragma unroll
                for (int ni = 0; ni < 4; ni++) {
                    const uint32_t* bh2 = &bH[ni >> 1][(ni & 1) * 2];
                    const uint32_t* bl2 = &bL[ni >> 1][(ni & 1) * 2];
                    mma16816(acc[mi][ni], aH[mi], bh2);
                    mma16816(acc[mi][ni], aH[mi], bl2);
                    mma16816(acc[mi][ni], aL[mi], bh2);
                }
        }
    }
    __syncthreads();
#undef ISSUE
}

// stage fp32 C tile into smem [128][132] for coalesced epilogues
static __device__ __forceinline__ void acc_to_smem(float (&acc)[4][4][4]) {
    extern __shared__ char smem[];
    float* ep = (float*)smem;
    const int lane = threadIdx.x & 31;
    const int wid  = threadIdx.x >> 5;
    const int wm = wid & 1, wn = wid >> 1;
#pragma unroll
    for (int mi = 0; mi < 4; mi++)
#pragma unroll
        for (int ni = 0; ni < 4; ni++) {
            const int r0 = wm * 64 + mi * 16 + (lane >> 2);
            const int c0 = wn * 32 + ni * 8 + (lane & 3) * 2;
            ep[r0 * EPI_STR + c0]           = acc[mi][ni][0];
            ep[r0 * EPI_STR + c0 + 1]       = acc[mi][ni][1];
            ep[(r0 + 8) * EPI_STR + c0]     = acc[mi][ni][2];
            ep[(r0 + 8) * EPI_STR + c0 + 1] = acc[mi][ni][3];
        }
    __syncthreads();
}

// ===================== fp32 -> bf16 hi/lo split ==============================
__global__ void __launch_bounds__(256)
cvt_kernel(const float* __restrict__ src, int which, int n) {
    __nv_bfloat16 *hi, *lo;
    switch (which) {
        case 0:  hi = g_xh;  lo = g_xl;  break;
        case 1:  hi = g_wqh; lo = g_wql; break;
        case 2:  hi = g_wkh; lo = g_wkl; break;
        case 3:  hi = g_wvh; lo = g_wvl; break;
        default: hi = g_wdh; lo = g_wdl; break;
    }
    int i0 = (blockIdx.x * 256 + threadIdx.x) * 4;
#pragma unroll
    for (int u = 0; u < 4; u++) {
        int i = i0 + u;
        if (i < n) split_bf(src[i], hi[i], lo[i]);
    }
}

// ===================== 1) QKV projection =====================================
__global__ void __launch_bounds__(256)
qkv_kernel(const float* __restrict__ pbq, const float* __restrict__ pbk,
           const float* __restrict__ pbv) {
    const int mode = blockIdx.z;
    const int m0 = blockIdx.y * 128, n0 = blockIdx.x * 128;
    const __nv_bfloat16* Wh = (mode == 0) ? g_wqh : (mode == 1) ? g_wkh : g_wvh;
    const __nv_bfloat16* Wl = (mode == 0) ? g_wql : (mode == 1) ? g_wkl : g_wvl;
    const float* bias = (mode == 0) ? pbq : (mode == 1) ? pbk : pbv;

    float acc[4][4][4] = {};
    mma_gemm(g_xh + (size_t)m0 * HIDDEN, g_xl + (size_t)m0 * HIDDEN,
             Wh + (size_t)n0 * HIDDEN, Wl + (size_t)n0 * HIDDEN,
             HIDDEN, HIDDEN, HIDDEN, acc);
    acc_to_smem(acc);

    extern __shared__ char smem[];
    const float* ep = (const float*)smem;
    const int tid = threadIdx.x;
    const int half = tid & 1;
    const int h = blockIdx.x;                   // 128-wide N block == one head

    if (mode == 2) {
        // vT: [bh][d][s]
        const int dcol = tid >> 1;
        const int b = m0 >> 11;
        const float bia = bias[n0 + dcol];
        const size_t base = ((size_t)(b * NHEADS + h) * HDIM + dcol) * SEQ +
                            (m0 & (SEQ - 1)) + half * 64;
#pragma unroll 8
        for (int s = 0; s < 64; s += 2) {
            float v0 = ep[(half * 64 + s) * EPI_STR + dcol] + bia;
            float v1 = ep[(half * 64 + s + 1) * EPI_STR + dcol] + bia;
            __nv_bfloat16 h0, l0, h1, l1;
            split_bf(v0, h0, l0); split_bf(v1, h1, l1);
            *(__nv_bfloat162*)(g_vTh + base + s) = __nv_bfloat162(h0, h1);
            *(__nv_bfloat162*)(g_vTl + base + s) = __nv_bfloat162(l0, l1);
        }
    } else {
        const int r = tid >> 1;
        const int m = m0 + r;
        const int b = m >> 11, s = m & (SEQ - 1);
        __nv_bfloat16* dh = (mode == 0) ? g_qh : g_kh;
        __nv_bfloat16* dl = (mode == 0) ? g_ql : g_kl;
        const size_t base = ((size_t)(b * NHEADS + h) * SEQ + s) * HDIM + half * 64;
        const float* er = ep + r * EPI_STR + half * 64;
        const float* bi = bias + n0 + half * 64;
#pragma unroll 8
        for (int cc = 0; cc < 64; cc += 2) {
            float v0 = er[cc] + bi[cc];
            float v1 = er[cc + 1] + bi[cc + 1];
            __nv_bfloat16 h0, l0, h1, l1;
            split_bf(v0, h0, l0); split_bf(v1, h1, l1);
            *(__nv_bfloat162*)(dh + base + cc) = __nv_bfloat162(h0, h1);
            *(__nv_bfloat162*)(dl + base + cc) = __nv_bfloat162(l0, l1);
        }
    }
}

// ===================== 2) scores = alibi + inv_norm * Q K^T ==================
__global__ void __launch_bounds__(256)
scores_kernel(const float* __restrict__ alibi) {
    const int z = blockIdx.z;
    const int m0 = blockIdx.y * 128, n0 = blockIdx.x * 128;
    const size_t zo = (size_t)z * SEQ * HDIM;

    float acc[4][4][4] = {};
    mma_gemm(g_qh + zo + (size_t)m0 * HDIM, g_ql + zo + (size_t)m0 * HDIM,
             g_kh + zo + (size_t)n0 * HDIM, g_kl + zo + (size_t)n0 * HDIM,
             HDIM, HDIM, HDIM, acc);
    acc_to_smem(acc);

    extern __shared__ char smem[];
    const float* ep = (const float*)smem;
    const int tid = threadIdx.x;
    const int r = tid >> 1, half = tid & 1;
    const float* al = alibi + (size_t)z * SEQ + n0 + half * 64;
    float* C = g_scores + (size_t)z * SEQ * SEQ +
               (size_t)(m0 + r) * SEQ + n0 + half * 64;
    const float* er = ep + r * EPI_STR + half * 64;
#pragma unroll 4
    for (int cc = 0; cc < 64; cc += 4) {
        float4 av = *(const float4*)(al + cc);
        float4 v;
        v.x = av.x + INV_NORM * er[cc + 0];
        v.y = av.y + INV_NORM * er[cc + 1];
        v.z = av.z + INV_NORM * er[cc + 2];
        v.w = av.w + INV_NORM * er[cc + 3];
        *(float4*)(C + cc) = v;
    }
}

// ===================== 3) softmax -> P hi/lo bf16 ============================
__global__ void __launch_bounds__(256)
softmax_kernel() {
    const size_t ro = (size_t)blockIdx.x * SEQ;
    const float* p = g_scores + ro;
    const int tid = threadIdx.x;
    __shared__ float red[256];

    float vals[8];
    float lmax = -INFINITY;
#pragma unroll
    for (int i = 0; i < 8; i++) {
        vals[i] = p[tid + i * 256];
        lmax = fmaxf(lmax, vals[i]);
    }
    red[tid] = lmax;
    __syncthreads();
    for (int s = 128; s > 0; s >>= 1) {
        if (tid < s) red[tid] = fmaxf(red[tid], red[tid + s]);
        __syncthreads();
    }
    const float rmax = red[0];
    __syncthreads();

    float lsum = 0.f;
#pragma unroll
    for (int i = 0; i < 8; i++) {
        vals[i] = __expf(vals[i] - rmax);
        lsum += vals[i];
    }
    red[tid] = lsum;
    __syncthreads();
    for (int s = 128; s > 0; s >>= 1) {
        if (tid < s) red[tid] += red[tid + s];
        __syncthreads();
    }
    const float rinv = 1.0f / red[0];
#pragma unroll
    for (int i = 0; i < 8; i++) {
        const float v = vals[i] * rinv;
        __nv_bfloat16 h, l;
        split_bf(v, h, l);
        g_ph[ro + tid + i * 256] = h;
        g_pl[ro + tid + i * 256] = l;
    }
}

// ===================== 4) ctx = P @ V -> bf16 hi/lo ==========================
__global__ void __launch_bounds__(256)
ctx_kernel() {
    const int z = blockIdx.z;
    const int m0 = blockIdx.y * 128;
    const size_t po = (size_t)z * SEQ * SEQ + (size_t)m0 * SEQ;
    const size_t vo = (size_t)z * HDIM * SEQ;

    float acc[4][4][4] = {};
    mma_gemm(g_ph + po, g_pl + po, g_vTh + vo, g_vTl + vo,
             SEQ, SEQ, SEQ, acc);
    acc_to_smem(acc);

    extern __shared__ char smem[];
    const float* ep = (const float*)smem;
    const int tid = threadIdx.x;
    const int r = tid >> 1, half = tid & 1;
    const int b = z / NHEADS, h = z % NHEADS;
    const size_t base = ((size_t)(b * SEQ + m0 + r)) * HIDDEN +
                        h * HDIM + half * 64;
    const float* er = ep + r * EPI_STR + half * 64;
#pragma unroll 8
    for (int cc = 0; cc < 64; cc += 2) {
        __nv_bfloat16 h0, l0, h1, l1;
        split_bf(er[cc], h0, l0); split_bf(er[cc + 1], h1, l1);
        *(__nv_bfloat162*)(g_ch + base + cc) = __nv_bfloat162(h0, h1);
        *(__nv_bfloat162*)(g_cl + base + cc) = __nv_bfloat162(l0, l1);
    }
}

// ===================== 5) out = ctx @ Wd^T + bd + residual ===================
__global__ void __launch_bounds__(256)
out_kernel(const float* __restrict__ bd, const float* __restrict__ residual,
           float* __restrict__ outp) {
    const int m0 = blockIdx.y * 128, n0 = blockIdx.x * 128;

    float acc[4][4][4] = {};
    mma_gemm(g_ch + (size_t)m0 * HIDDEN, g_cl + (size_t)m0 * HIDDEN,
             g_wdh + (size_t)n0 * HIDDEN, g_wdl + (size_t)n0 * HIDDEN,
             HIDDEN, HIDDEN, HIDDEN, acc);
    acc_to_smem(acc);

    extern __shared__ char smem[];
    const float* ep = (const float*)smem;
    const int tid = threadIdx.x;
    const int r = tid >> 1, half = tid & 1;
    const size_t idx = (size_t)(m0 + r) * HIDDEN + n0 + half * 64;
    const float* er = ep + r * EPI_STR + half * 64;
    const float* bi = bd + n0 + half * 64;
    const float* rs = residual + idx;
    float* dst = outp + idx;
#pragma unroll 4
    for (int cc = 0; cc < 64; cc += 4) {
        float4 bv = *(const float4*)(bi + cc);
        float4 rv = *(const float4*)(rs + cc);
        float4 v;
        v.x = er[cc + 0] + bv.x + rv.x;
        v.y = er[cc + 1] + bv.y + rv.y;
        v.z = er[cc + 2] + bv.z + rv.z;
        v.w = er[cc + 3] + bv.w + rv.w;
        *(float4*)(dst + cc) = v;
    }
}

// ===================== launch =================================================
extern "C" void kernel_launch(void* const* d_in, const int* in_sizes, int n_in,
                              void* d_out, int out_size) {
    const float* X        = (const float*)d_in[0];
    const float* residual = (const float*)d_in[1];
    const float* alibi    = (const float*)d_in[2];
    const float* Wq = (const float*)d_in[3];  const float* bq = (const float*)d_in[4];
    const float* Wk = (const float*)d_in[5];  const float* bk = (const float*)d_in[6];
    const float* Wv = (const float*)d_in[7];  const float* bv = (const float*)d_in[8];
    const float* Wd = (const float*)d_in[9];  const float* bd = (const float*)d_in[10];
    float* out = (float*)d_out;

    cudaFuncSetAttribute(qkv_kernel, cudaFuncAttributeMaxDynamicSharedMemorySize, SMEM_DYN);
    cudaFuncSetAttribute(scores_kernel, cudaFuncAttributeMaxDynamicSharedMemorySize, SMEM_DYN);
    cudaFuncSetAttribute(ctx_kernel, cudaFuncAttributeMaxDynamicSharedMemorySize, SMEM_DYN);
    cudaFuncSetAttribute(out_kernel, cudaFuncAttributeMaxDynamicSharedMemorySize, SMEM_DYN);

    dim3 blk(256);
    const int nX = MROWS * HIDDEN;
    const int nW = HIDDEN * HIDDEN;
    cvt_kernel<<<nX / 1024, blk>>>(X,  0, nX);
    cvt_kernel<<<nW / 1024, blk>>>(Wq, 1, nW);
    cvt_kernel<<<nW / 1024, blk>>>(Wk, 2, nW);
    cvt_kernel<<<nW / 1024, blk>>>(Wv, 3, nW);
    cvt_kernel<<<nW / 1024, blk>>>(Wd, 4, nW);

    qkv_kernel<<<dim3(16, 32, 3), blk, SMEM_DYN>>>(bq, bk, bv);
    scores_kernel<<<dim3(16, 16, 32), blk, SMEM_DYN>>>(alibi);
    softmax_kernel<<<dim3(BH * SEQ), blk>>>();
    ctx_kernel<<<dim3(1, 16, 32), blk, SMEM_DYN>>>();
    out_kernel<<<dim3(16, 32), blk, SMEM_DYN>>>(bd, residual, out);
}